// round 2
// baseline (speedup 1.0000x reference)
#include <cuda_runtime.h>
#include <cuda_bf16.h>

// Stable counting-sort of N rows by 4-class label, margin-adjust the
// true-class logit, emit (sorted data [N,4], sorted labels as float [N],
// scalar mean-NLL loss). Output: [data | labels | loss] float32.
//
// 2 kernels:
//   K1 histScan: per-block 4-bin histogram; last block scans all hists into
//                per-block/per-class global offsets, zeroes loss accum.
//   K2 scatter:  phase A ballots -> per-(iter,warp) counts; one block scan;
//                phase B barrier-free scatter + fused loss; last block writes
//                the final loss scalar.

constexpr int TPB = 256;
constexpr int ROWS_PER_THREAD = 16;
constexpr int ROWS_PER_BLOCK = TPB * ROWS_PER_THREAD;   // 4096
constexpr int NW = TPB / 32;                            // 8 warps
constexpr int MAX_BLOCKS = 8192;

__device__ int4 g_blockHist[MAX_BLOCKS];
__device__ int4 g_blockOffset[MAX_BLOCKS];
__device__ double g_loss;
__device__ unsigned g_histDone;
__device__ unsigned g_scatDone;

static __device__ __forceinline__ int4 add4(int4 a, int4 b) {
    return make_int4(a.x + b.x, a.y + b.y, a.z + b.z, a.w + b.w);
}

// ---------------------------------------------------------------------------
// K1: per-block histogram (int4-vectorized label reads) + last-block scan
// ---------------------------------------------------------------------------
__global__ void __launch_bounds__(TPB) histScanKernel(const int* __restrict__ label,
                                                      int n, int numBlocks) {
    int tid = threadIdx.x;
    int c0 = 0, c1 = 0, c2 = 0, c3 = 0;

    int vbase = blockIdx.x * (ROWS_PER_BLOCK / 4);   // int4 index base
    int nv4 = n >> 2;                                // n is a multiple of 4 here
#pragma unroll
    for (int k = 0; k < ROWS_PER_THREAD / 4; ++k) {
        int vi = vbase + k * TPB + tid;
        if (vi < nv4) {
            int4 L = reinterpret_cast<const int4*>(label)[vi];
            c0 += (L.x == 0) + (L.y == 0) + (L.z == 0) + (L.w == 0);
            c1 += (L.x == 1) + (L.y == 1) + (L.z == 1) + (L.w == 1);
            c2 += (L.x == 2) + (L.y == 2) + (L.z == 2) + (L.w == 2);
            c3 += (L.x == 3) + (L.y == 3) + (L.z == 3) + (L.w == 3);
        }
    }
#pragma unroll
    for (int off = 16; off > 0; off >>= 1) {
        c0 += __shfl_down_sync(0xffffffffu, c0, off);
        c1 += __shfl_down_sync(0xffffffffu, c1, off);
        c2 += __shfl_down_sync(0xffffffffu, c2, off);
        c3 += __shfl_down_sync(0xffffffffu, c3, off);
    }
    __shared__ int sh[4];
    if (tid < 4) sh[tid] = 0;
    __syncthreads();
    if ((tid & 31) == 0) {
        atomicAdd(&sh[0], c0); atomicAdd(&sh[1], c1);
        atomicAdd(&sh[2], c2); atomicAdd(&sh[3], c3);
    }
    __syncthreads();
    if (tid == 0)
        g_blockHist[blockIdx.x] = make_int4(sh[0], sh[1], sh[2], sh[3]);

    // last block performs the global scan
    __threadfence();
    __shared__ bool isLast;
    if (tid == 0) {
        unsigned t = atomicAdd(&g_histDone, 1u);
        isLast = (t == (unsigned)(gridDim.x - 1));
        if (isLast) g_histDone = 0;   // reset for graph replay
    }
    __syncthreads();
    if (!isLast) return;

    __shared__ int4 ss[TPB];
    int chunk = (numBlocks + TPB - 1) / TPB;
    int start = tid * chunk;
    int end = min(start + chunk, numBlocks);

    int4 s = make_int4(0, 0, 0, 0);
    for (int j = start; j < end; ++j) s = add4(s, g_blockHist[j]);
    ss[tid] = s;
    __syncthreads();
    for (int off = 1; off < TPB; off <<= 1) {
        int4 v = ss[tid];
        if (tid >= off) v = add4(v, ss[tid - off]);
        __syncthreads();
        ss[tid] = v;
        __syncthreads();
    }
    int4 incl = ss[tid];
    int4 tot = ss[TPB - 1];
    int4 run;
    run.x = (incl.x - s.x);
    run.y = (incl.y - s.y) + tot.x;
    run.z = (incl.z - s.z) + tot.x + tot.y;
    run.w = (incl.w - s.w) + tot.x + tot.y + tot.z;

    for (int j = start; j < end; ++j) {
        int4 h = g_blockHist[j];
        g_blockOffset[j] = run;
        run = add4(run, h);
    }
    if (tid == 0) { g_loss = 0.0; g_scatDone = 0; }
}

// ---------------------------------------------------------------------------
// K2: barrier-light stable scatter + fused loss
// ---------------------------------------------------------------------------
__global__ void __launch_bounds__(TPB) scatterKernel(const float* __restrict__ data,
                                                     const int* __restrict__ label,
                                                     float* __restrict__ outData,
                                                     float* __restrict__ outLabel,
                                                     float* __restrict__ outLoss,
                                                     int n) {
    __shared__ int4 shCnt[ROWS_PER_THREAD * NW];   // [it][w], 128 entries
    __shared__ int blockOff[4];
    __shared__ float warpLoss[NW];

    int tid = threadIdx.x;
    int w = tid >> 5;
    int lane = tid & 31;
    unsigned laneLT = (1u << lane) - 1u;
    int base = blockIdx.x * ROWS_PER_BLOCK;

    if (tid < 4) {
        const int* bo = reinterpret_cast<const int*>(g_blockOffset);
        blockOff[tid] = bo[blockIdx.x * 4 + tid];
    }

    // ---- Phase A: labels -> ballots -> per-(it,warp) counts -----------------
    unsigned cpack = 0;                 // 2 bits per iteration: class
    unsigned wrp[ROWS_PER_THREAD / 4];  // 8 bits per iteration: warp rank
#pragma unroll
    for (int k = 0; k < ROWS_PER_THREAD / 4; ++k) wrp[k] = 0;

#pragma unroll
    for (int it = 0; it < ROWS_PER_THREAD; ++it) {
        int idx = base + it * TPB + tid;
        int c = (idx < n) ? label[idx] : 4;

        unsigned m0 = __ballot_sync(0xffffffffu, c == 0);
        unsigned m1 = __ballot_sync(0xffffffffu, c == 1);
        unsigned m2 = __ballot_sync(0xffffffffu, c == 2);
        unsigned m3 = __ballot_sync(0xffffffffu, c == 3);
        if (lane == 0)
            shCnt[it * NW + w] = make_int4(__popc(m0), __popc(m1),
                                           __popc(m2), __popc(m3));
        unsigned myM = (c == 0) ? m0 : (c == 1) ? m1 : (c == 2) ? m2 : m3;
        unsigned wr = __popc(myM & laneLT);
        cpack |= (unsigned)(c & 3) << (it * 2);
        wrp[it >> 2] |= wr << ((it & 3) * 8);
    }
    __syncthreads();

    // ---- block scan over 128 int4 entries (it-major, then warp) -------------
    {
        int4 own = make_int4(0, 0, 0, 0);
        if (tid < ROWS_PER_THREAD * NW) own = shCnt[tid];
#pragma unroll
        for (int off = 1; off < ROWS_PER_THREAD * NW; off <<= 1) {
            int4 v = make_int4(0, 0, 0, 0);
            if (tid < ROWS_PER_THREAD * NW) {
                v = shCnt[tid];
                if (tid >= off) v = add4(v, shCnt[tid - off]);
            }
            __syncthreads();
            if (tid < ROWS_PER_THREAD * NW) shCnt[tid] = v;
            __syncthreads();
        }
        // convert inclusive -> exclusive
        if (tid < ROWS_PER_THREAD * NW) {
            int4 incl = shCnt[tid];
            shCnt[tid] = make_int4(incl.x - own.x, incl.y - own.y,
                                   incl.z - own.z, incl.w - own.w);
        }
        __syncthreads();
    }

    // ---- Phase B: barrier-free scatter + loss -------------------------------
    float lsum = 0.0f;
#pragma unroll
    for (int it = 0; it < ROWS_PER_THREAD; ++it) {
        int idx = base + it * TPB + tid;
        if (idx < n) {
            int c = (cpack >> (it * 2)) & 3;
            int wr = (wrp[it >> 2] >> ((it & 3) * 8)) & 0xff;
            int4 ex = shCnt[it * NW + w];
            int pre = (c == 0) ? ex.x : (c == 1) ? ex.y : (c == 2) ? ex.z : ex.w;
            int dest = blockOff[c] + pre + wr;

            float4 r = reinterpret_cast<const float4*>(data)[idx];
            float v = (c == 0) ? r.x : (c == 1) ? r.y : (c == 2) ? r.z : r.w;
            float adj = (v > 0.0f) ? v * (1.0f / 4.00001f) - 0.5f
                                   : v * 4.00001f - 0.5f;
            if (c == 0) r.x = adj; else if (c == 1) r.y = adj;
            else if (c == 2) r.z = adj; else r.w = adj;

            float mx = fmaxf(fmaxf(r.x, r.y), fmaxf(r.z, r.w));
            float lse = mx + logf(expf(r.x - mx) + expf(r.y - mx) +
                                  expf(r.z - mx) + expf(r.w - mx));
            lsum += lse - adj;   // -log p[true]

            reinterpret_cast<float4*>(outData)[dest] = r;
            outLabel[dest] = (float)c;
        }
    }

    // ---- loss reduction -----------------------------------------------------
#pragma unroll
    for (int off = 16; off > 0; off >>= 1)
        lsum += __shfl_down_sync(0xffffffffu, lsum, off);
    if (lane == 0) warpLoss[w] = lsum;
    __syncthreads();
    if (tid == 0) {
        double s = 0.0;
#pragma unroll
        for (int ww = 0; ww < NW; ++ww) s += (double)warpLoss[ww];
        atomicAdd(&g_loss, s);
    }

    // ---- last block writes the loss scalar ----------------------------------
    __threadfence();
    __shared__ bool isLast;
    if (tid == 0) {
        unsigned t = atomicAdd(&g_scatDone, 1u);
        isLast = (t == (unsigned)(gridDim.x - 1));
        if (isLast) g_scatDone = 0;
    }
    __syncthreads();
    if (isLast && tid == 0) {
        double L = *((volatile double*)&g_loss);
        outLoss[0] = (float)(L / (double)n);
    }
}

extern "C" void kernel_launch(void* const* d_in, const int* in_sizes, int n_in,
                              void* d_out, int out_size) {
    const float* data = (const float*)d_in[0];
    const int* label = (const int*)d_in[1];
    float* out = (float*)d_out;
    int n = in_sizes[1];

    int nb = (n + ROWS_PER_BLOCK - 1) / ROWS_PER_BLOCK;

    histScanKernel<<<nb, TPB>>>(label, n, nb);
    scatterKernel<<<nb, TPB>>>(data, label, out, out + (size_t)n * 4,
                               out + (size_t)n * 5, n);
}

// round 3
// speedup vs baseline: 1.3162x; 1.3162x over previous
#include <cuda_runtime.h>
#include <cuda_bf16.h>

// Stable counting-sort of N rows by 4-class label, margin-adjust the
// true-class logit, emit (sorted data [N,4], sorted labels as float [N],
// scalar mean-NLL loss). Output: [data | labels | loss] float32.
//
// Design: warp-private chunks. K1 builds a per-WARP 4-bin histogram and its
// last block scans them into per-warp global class offsets. K2's hot loop is
// barrier-free: ballot ranks + 4 running scalars per warp; labels output is
// written analytically from class boundaries (streaming, no scatter).

constexpr int TPB = 256;
constexpr int WPB = TPB / 32;              // 8 warps/block
constexpr int RPW = 1024;                  // rows per warp
constexpr int ITERS = RPW / 32;            // 32
constexpr int ROWS_PER_BLOCK = WPB * RPW;  // 8192
constexpr int MAX_WARPS = 16384;

__device__ int4 g_warpHist[MAX_WARPS];
__device__ int4 g_warpOffset[MAX_WARPS];
__device__ int4 g_classBase;               // global start of each class
__device__ double g_loss;
__device__ unsigned g_histDone;
__device__ unsigned g_scatDone;

static __device__ __forceinline__ int4 add4(int4 a, int4 b) {
    return make_int4(a.x + b.x, a.y + b.y, a.z + b.z, a.w + b.w);
}

// ---------------------------------------------------------------------------
// K1: per-warp histogram + last-block scan into per-warp offsets
// ---------------------------------------------------------------------------
__global__ void __launch_bounds__(TPB) histScanKernel(const int* __restrict__ label,
                                                      int n, int numWarps) {
    int tid = threadIdx.x;
    int w = tid >> 5;
    int lane = tid & 31;
    int gw = blockIdx.x * WPB + w;            // global warp id
    int nv4 = n >> 2;

    int c0 = 0, c1 = 0, c2 = 0, c3 = 0;
    int base4 = gw * (RPW / 4);
#pragma unroll
    for (int k = 0; k < RPW / 128; ++k) {     // 8 int4 loads per lane
        int vi = base4 + k * 32 + lane;
        if (vi < nv4) {
            int4 L = reinterpret_cast<const int4*>(label)[vi];
            c0 += (L.x == 0) + (L.y == 0) + (L.z == 0) + (L.w == 0);
            c1 += (L.x == 1) + (L.y == 1) + (L.z == 1) + (L.w == 1);
            c2 += (L.x == 2) + (L.y == 2) + (L.z == 2) + (L.w == 2);
            c3 += (L.x == 3) + (L.y == 3) + (L.z == 3) + (L.w == 3);
        }
    }
#pragma unroll
    for (int off = 16; off > 0; off >>= 1) {
        c0 += __shfl_down_sync(0xffffffffu, c0, off);
        c1 += __shfl_down_sync(0xffffffffu, c1, off);
        c2 += __shfl_down_sync(0xffffffffu, c2, off);
        c3 += __shfl_down_sync(0xffffffffu, c3, off);
    }
    if (lane == 0) g_warpHist[gw] = make_int4(c0, c1, c2, c3);

    // ---- last block scans all per-warp hists --------------------------------
    __threadfence();
    __shared__ bool isLast;
    if (tid == 0) {
        unsigned t = atomicAdd(&g_histDone, 1u);
        isLast = (t == (unsigned)(gridDim.x - 1));
        if (isLast) g_histDone = 0;           // reset for graph replay
    }
    __syncthreads();
    if (!isLast) return;

    __shared__ int4 ss[TPB];
    int chunk = (numWarps + TPB - 1) / TPB;
    int start = tid * chunk;
    int end = min(start + chunk, numWarps);

    int4 s = make_int4(0, 0, 0, 0);
    for (int j = start; j < end; ++j) s = add4(s, g_warpHist[j]);
    ss[tid] = s;
    __syncthreads();
    for (int off = 1; off < TPB; off <<= 1) {
        int4 v = ss[tid];
        if (tid >= off) v = add4(v, ss[tid - off]);
        __syncthreads();
        ss[tid] = v;
        __syncthreads();
    }
    int4 incl = ss[tid];
    int4 tot = ss[TPB - 1];
    int4 run;
    run.x = (incl.x - s.x);
    run.y = (incl.y - s.y) + tot.x;
    run.z = (incl.z - s.z) + tot.x + tot.y;
    run.w = (incl.w - s.w) + tot.x + tot.y + tot.z;

    for (int j = start; j < end; ++j) {
        int4 h = g_warpHist[j];
        g_warpOffset[j] = run;
        run = add4(run, h);
    }
    if (tid == 0) {
        g_classBase = make_int4(0, tot.x, tot.x + tot.y, tot.x + tot.y + tot.z);
        g_loss = 0.0;
        g_scatDone = 0;
    }
}

// ---------------------------------------------------------------------------
// K2: barrier-free warp-private scatter + analytic label fill + fused loss
// ---------------------------------------------------------------------------
__global__ void __launch_bounds__(TPB) scatterKernel(const float* __restrict__ data,
                                                     const int* __restrict__ label,
                                                     float* __restrict__ outData,
                                                     float* __restrict__ outLabel,
                                                     float* __restrict__ outLoss,
                                                     int n) {
    int tid = threadIdx.x;
    int w = tid >> 5;
    int lane = tid & 31;
    unsigned laneLT = (1u << lane) - 1u;
    int gw = blockIdx.x * WPB + w;

    // per-warp running destination offsets (all lanes keep identical copies)
    int4 wo = g_warpOffset[gw];
    int off0 = wo.x, off1 = wo.y, off2 = wo.z, off3 = wo.w;

    int rowBase = gw * RPW;
    float lsum = 0.0f;

#pragma unroll 4
    for (int it = 0; it < ITERS; ++it) {
        int idx = rowBase + it * 32 + lane;
        bool valid = idx < n;
        int c = valid ? label[idx] : 4;

        unsigned m0 = __ballot_sync(0xffffffffu, c == 0);
        unsigned m1 = __ballot_sync(0xffffffffu, c == 1);
        unsigned m2 = __ballot_sync(0xffffffffu, c == 2);
        unsigned m3 = __ballot_sync(0xffffffffu, c == 3);

        if (valid) {
            unsigned myM = (c == 0) ? m0 : (c == 1) ? m1 : (c == 2) ? m2 : m3;
            int base = (c == 0) ? off0 : (c == 1) ? off1 : (c == 2) ? off2 : off3;
            int dest = base + __popc(myM & laneLT);

            float4 r = reinterpret_cast<const float4*>(data)[idx];
            float v = (c == 0) ? r.x : (c == 1) ? r.y : (c == 2) ? r.z : r.w;
            float adj = (v > 0.0f) ? v * (1.0f / 4.00001f) - 0.5f
                                   : v * 4.00001f - 0.5f;
            if (c == 0) r.x = adj; else if (c == 1) r.y = adj;
            else if (c == 2) r.z = adj; else r.w = adj;

            float mx = fmaxf(fmaxf(r.x, r.y), fmaxf(r.z, r.w));
            float lse = mx + __logf(__expf(r.x - mx) + __expf(r.y - mx) +
                                    __expf(r.z - mx) + __expf(r.w - mx));
            lsum += lse - adj;    // -log p[true]

            reinterpret_cast<float4*>(outData)[dest] = r;
        }
        off0 += __popc(m0); off1 += __popc(m1);
        off2 += __popc(m2); off3 += __popc(m3);
    }

    // ---- analytic sorted-label fill (streaming float4 stores) ---------------
    {
        int4 cb = g_classBase;
        int b1 = cb.y, b2 = cb.z, b3 = cb.w;
        int blkBase = blockIdx.x * ROWS_PER_BLOCK;
#pragma unroll
        for (int k = 0; k < ROWS_PER_BLOCK / (TPB * 4); ++k) {  // 8 float4/thread
            int p = blkBase + (k * TPB + tid) * 4;
            if (p < n) {
                float4 o;
                o.x = (float)((p     >= b1) + (p     >= b2) + (p     >= b3));
                o.y = (float)((p + 1 >= b1) + (p + 1 >= b2) + (p + 1 >= b3));
                o.z = (float)((p + 2 >= b1) + (p + 2 >= b2) + (p + 2 >= b3));
                o.w = (float)((p + 3 >= b1) + (p + 3 >= b2) + (p + 3 >= b3));
                reinterpret_cast<float4*>(outLabel)[p >> 2] = o;
            }
        }
    }

    // ---- loss reduction: warp -> block -> one double atomic -----------------
    __shared__ float warpLoss[WPB];
#pragma unroll
    for (int off = 16; off > 0; off >>= 1)
        lsum += __shfl_down_sync(0xffffffffu, lsum, off);
    if (lane == 0) warpLoss[w] = lsum;
    __syncthreads();
    if (tid == 0) {
        double s = 0.0;
#pragma unroll
        for (int ww = 0; ww < WPB; ++ww) s += (double)warpLoss[ww];
        atomicAdd(&g_loss, s);
    }

    // ---- last block writes the loss scalar ----------------------------------
    __threadfence();
    __shared__ bool isLast;
    if (tid == 0) {
        unsigned t = atomicAdd(&g_scatDone, 1u);
        isLast = (t == (unsigned)(gridDim.x - 1));
        if (isLast) g_scatDone = 0;
    }
    __syncthreads();
    if (isLast && tid == 0) {
        double L = *((volatile double*)&g_loss);
        outLoss[0] = (float)(L / (double)n);
    }
}

extern "C" void kernel_launch(void* const* d_in, const int* in_sizes, int n_in,
                              void* d_out, int out_size) {
    const float* data = (const float*)d_in[0];
    const int* label = (const int*)d_in[1];
    float* out = (float*)d_out;
    int n = in_sizes[1];

    int nb = (n + ROWS_PER_BLOCK - 1) / ROWS_PER_BLOCK;
    int numWarps = nb * WPB;

    histScanKernel<<<nb, TPB>>>(label, n, numWarps);
    scatterKernel<<<nb, TPB>>>(data, label, out, out + (size_t)n * 4,
                               out + (size_t)n * 5, n);
}

// round 4
// speedup vs baseline: 1.3933x; 1.0585x over previous
#include <cuda_runtime.h>
#include <cuda_bf16.h>

// Single persistent kernel: stable 4-class counting sort + margin adjust +
// fused mean-NLL loss. Output: [data[N,4] | labels[N] | loss] float32.
//
// Phase 1: read labels once, cache packed classes in smem, per-tile hists.
// Grid sync: last-arriving block scans tile hists -> per-tile offsets, flag.
// Phase 2: barrier-free ballot-rank scatter from smem classes + analytic
//          sorted-label fill + loss; last-done block writes the scalar.

constexpr int TPB = 256;
constexpr int WPB = 8;                 // warps per block
constexpr int TILE = 1024;             // rows per tile
constexpr int RPW_T = TILE / WPB;      // 128 rows per warp per tile
constexpr int T_PB_MAX = 12;           // max tiles per block (smem bound)
constexpr int MAX_TILES = 16384;
constexpr int RESIDENT_BPSM = 6;       // forced co-residency

__device__ int4 g_tileHist[MAX_TILES];
__device__ int4 g_tileOff[MAX_TILES];
__device__ int4 g_classBase;
__device__ double g_loss;
__device__ unsigned g_histDone;
__device__ unsigned g_scatDone;
__device__ volatile unsigned g_flag;

static __device__ __forceinline__ int4 add4(int4 a, int4 b) {
    return make_int4(a.x + b.x, a.y + b.y, a.z + b.z, a.w + b.w);
}

__global__ void __launch_bounds__(TPB, RESIDENT_BPSM)
fusedKernel(const float* __restrict__ data, const int* __restrict__ label,
            float* __restrict__ outData, float* __restrict__ outLabel,
            float* __restrict__ outLoss, int n, int numTiles) {
    __shared__ unsigned char sClass[T_PB_MAX][TILE / 4];  // 2 bits/row packed
    __shared__ int4 sWarpHist[T_PB_MAX][WPB];
    __shared__ float warpLoss[WPB];
    __shared__ bool sScan;

    int tid = threadIdx.x;
    int w = tid >> 5;
    int lane = tid & 31;
    unsigned laneLT = (1u << lane) - 1u;

    // balanced contiguous tile range for this block
    int t0 = (int)(((long long)blockIdx.x * numTiles) / gridDim.x);
    int t1 = (int)(((long long)(blockIdx.x + 1) * numTiles) / gridDim.x);
    int nt = t1 - t0;                       // <= T_PB_MAX by host-side grid choice
    int nv4 = n >> 2;

    // ---------------- Phase 1: labels -> smem classes + tile hists ----------
    for (int s = 0; s < nt; ++s) {
        int tile = t0 + s;
        int vi = ((tile * TILE + w * RPW_T) >> 2) + lane;   // 1 int4 per lane
        int c0 = 0, c1 = 0, c2 = 0, c3 = 0;
        unsigned byte = 0;
        if (vi < nv4) {
            int4 L = reinterpret_cast<const int4*>(label)[vi];
            byte = (unsigned)(L.x | (L.y << 2) | (L.z << 4) | (L.w << 6));
            c0 = (L.x == 0) + (L.y == 0) + (L.z == 0) + (L.w == 0);
            c1 = (L.x == 1) + (L.y == 1) + (L.z == 1) + (L.w == 1);
            c2 = (L.x == 2) + (L.y == 2) + (L.z == 2) + (L.w == 2);
            c3 = (L.x == 3) + (L.y == 3) + (L.z == 3) + (L.w == 3);
        }
        sClass[s][w * 32 + lane] = (unsigned char)byte;
#pragma unroll
        for (int off = 16; off > 0; off >>= 1) {
            c0 += __shfl_down_sync(0xffffffffu, c0, off);
            c1 += __shfl_down_sync(0xffffffffu, c1, off);
            c2 += __shfl_down_sync(0xffffffffu, c2, off);
            c3 += __shfl_down_sync(0xffffffffu, c3, off);
        }
        if (lane == 0) sWarpHist[s][w] = make_int4(c0, c1, c2, c3);
    }
    __syncthreads();
    if (tid < nt) {                         // per-tile hist = sum of 8 warp hists
        int4 sum = make_int4(0, 0, 0, 0);
#pragma unroll
        for (int ww = 0; ww < WPB; ++ww) sum = add4(sum, sWarpHist[tid][ww]);
        g_tileHist[t0 + tid] = sum;
    }

    // ---------------- Grid sync + scan by last-arriving block ---------------
    __threadfence();
    if (tid == 0) {
        unsigned t = atomicAdd(&g_histDone, 1u);
        sScan = (t == gridDim.x - 1);
        if (sScan) g_histDone = 0;          // reset for graph replay
    }
    __syncthreads();

    if (sScan) {
        __shared__ int4 ss[TPB];
        int chunk = (numTiles + TPB - 1) / TPB;
        int start = tid * chunk;
        int end = min(start + chunk, numTiles);
        int4 s = make_int4(0, 0, 0, 0);
        for (int j = start; j < end; ++j) s = add4(s, g_tileHist[j]);
        ss[tid] = s;
        __syncthreads();
        for (int off = 1; off < TPB; off <<= 1) {
            int4 v = ss[tid];
            if (tid >= off) v = add4(v, ss[tid - off]);
            __syncthreads();
            ss[tid] = v;
            __syncthreads();
        }
        int4 incl = ss[tid];
        int4 tot = ss[TPB - 1];
        int4 run;
        run.x = (incl.x - s.x);
        run.y = (incl.y - s.y) + tot.x;
        run.z = (incl.z - s.z) + tot.x + tot.y;
        run.w = (incl.w - s.w) + tot.x + tot.y + tot.z;
        for (int j = start; j < end; ++j) {
            int4 h = g_tileHist[j];
            g_tileOff[j] = run;
            run = add4(run, h);
        }
        if (tid == 0) {
            g_classBase = make_int4(0, tot.x, tot.x + tot.y,
                                    tot.x + tot.y + tot.z);
            g_loss = 0.0;
        }
        __syncthreads();
        __threadfence();
        if (tid == 0) g_flag = 1;           // release
    } else {
        if (tid == 0) {
            while (g_flag == 0) __nanosleep(64);
        }
        __syncthreads();
        __threadfence();                    // acquire
    }

    // ---------------- Phase 2: scatter + labels + loss ----------------------
    int4 cb = g_classBase;
    float lsum = 0.0f;

    for (int s = 0; s < nt; ++s) {
        int tile = t0 + s;
        int4 to = g_tileOff[tile];
        int off0 = to.x, off1 = to.y, off2 = to.z, off3 = to.w;
        for (int ww = 0; ww < w; ++ww) {    // warp offset within tile
            int4 h = sWarpHist[s][ww];
            off0 += h.x; off1 += h.y; off2 += h.z; off3 += h.w;
        }
        int rowBase = tile * TILE + w * RPW_T;

#pragma unroll
        for (int it = 0; it < RPW_T / 32; ++it) {   // 4 iterations
            int idx = rowBase + it * 32 + lane;
            bool valid = idx < n;
            unsigned byte = sClass[s][w * 32 + it * 8 + (lane >> 2)];
            int c = (byte >> (2 * (lane & 3))) & 3;

            unsigned m0 = __ballot_sync(0xffffffffu, valid && c == 0);
            unsigned m1 = __ballot_sync(0xffffffffu, valid && c == 1);
            unsigned m2 = __ballot_sync(0xffffffffu, valid && c == 2);
            unsigned m3 = __ballot_sync(0xffffffffu, valid && c == 3);

            if (valid) {
                unsigned myM = (c == 0) ? m0 : (c == 1) ? m1 : (c == 2) ? m2 : m3;
                int base = (c == 0) ? off0 : (c == 1) ? off1
                         : (c == 2) ? off2 : off3;
                int dest = base + __popc(myM & laneLT);

                float4 r = reinterpret_cast<const float4*>(data)[idx];
                float v = (c == 0) ? r.x : (c == 1) ? r.y
                        : (c == 2) ? r.z : r.w;
                float adj = (v > 0.0f) ? v * (1.0f / 4.00001f) - 0.5f
                                       : v * 4.00001f - 0.5f;
                if (c == 0) r.x = adj; else if (c == 1) r.y = adj;
                else if (c == 2) r.z = adj; else r.w = adj;

                float mx = fmaxf(fmaxf(r.x, r.y), fmaxf(r.z, r.w));
                float lse = mx + __logf(__expf(r.x - mx) + __expf(r.y - mx) +
                                        __expf(r.z - mx) + __expf(r.w - mx));
                lsum += lse - adj;          // -log p[true]

                reinterpret_cast<float4*>(outData)[dest] = r;
            }
            off0 += __popc(m0); off1 += __popc(m1);
            off2 += __popc(m2); off3 += __popc(m3);
        }

        // analytic sorted-label fill for this tile (streaming float4)
        {
            int p = tile * TILE + tid * 4;
            if (p < n) {
                float4 o;
                o.x = (float)((p     >= cb.y) + (p     >= cb.z) + (p     >= cb.w));
                o.y = (float)((p + 1 >= cb.y) + (p + 1 >= cb.z) + (p + 1 >= cb.w));
                o.z = (float)((p + 2 >= cb.y) + (p + 2 >= cb.z) + (p + 2 >= cb.w));
                o.w = (float)((p + 3 >= cb.y) + (p + 3 >= cb.z) + (p + 3 >= cb.w));
                reinterpret_cast<float4*>(outLabel)[p >> 2] = o;
            }
        }
    }

    // ---------------- loss reduce + final scalar -----------------------------
#pragma unroll
    for (int off = 16; off > 0; off >>= 1)
        lsum += __shfl_down_sync(0xffffffffu, lsum, off);
    if (lane == 0) warpLoss[w] = lsum;
    __syncthreads();
    if (tid == 0) {
        double sum = 0.0;
#pragma unroll
        for (int ww = 0; ww < WPB; ++ww) sum += (double)warpLoss[ww];
        atomicAdd(&g_loss, sum);
    }

    __threadfence();
    __shared__ bool isLast;
    if (tid == 0) {
        unsigned t = atomicAdd(&g_scatDone, 1u);
        isLast = (t == gridDim.x - 1);
    }
    __syncthreads();
    if (isLast && tid == 0) {
        g_scatDone = 0;
        g_flag = 0;                         // reset for next replay
        double L = *((volatile double*)&g_loss);
        outLoss[0] = (float)(L / (double)n);
    }
}

extern "C" void kernel_launch(void* const* d_in, const int* in_sizes, int n_in,
                              void* d_out, int out_size) {
    const float* data = (const float*)d_in[0];
    const int* label = (const int*)d_in[1];
    float* out = (float*)d_out;
    int n = in_sizes[1];

    int sms = 148;
    cudaDeviceGetAttribute(&sms, cudaDevAttrMultiProcessorCount, 0);

    int numTiles = (n + TILE - 1) / TILE;
    int grid = sms * RESIDENT_BPSM;
    if (grid > numTiles) grid = numTiles;
    int minGrid = (numTiles + T_PB_MAX - 1) / T_PB_MAX;
    if (grid < minGrid) grid = minGrid;     // keeps nt <= T_PB_MAX

    fusedKernel<<<grid, TPB>>>(data, label, out, out + (size_t)n * 4,
                               out + (size_t)n * 5, n, numTiles);
}